// round 7
// baseline (speedup 1.0000x reference)
#include <cuda_runtime.h>
#include <cuda_bf16.h>
#include <cstdint>

#define NNODES 100000
#define MHE    200000
#define NEDGE  2000000

#define SA 136              // padded row stride (bf16 elems) for A and B tiles

// ---------------- scratch (static __device__) ----------------
static __device__ __align__(16) float4 g_she[2 * MHE * 4];
static __device__ __align__(16) float4 g_agg[2 * NNODES * 4];
static __device__ __align__(16) float  g_bdeg[2 * MHE];
static __device__ __align__(16) float  g_ddeg[2 * NNODES];
static __device__ __align__(16) float  g_Wcm[2048];              // [32][64]
static __device__ __align__(16) float  g_bprime[64];
static __device__ __align__(16) __nv_bfloat16 g_Bh[256 * SA];    // B hi, padded row-major [n][k]
static __device__ __align__(16) __nv_bfloat16 g_Bl[256 * SA];    // B lo
static __device__ __align__(16) float  g_br[64], g_bz[64], g_bni[64], g_bnh[64];

// smem byte offsets for k_gru
#define A_HI_OFF   0                 // 128*SA*2 = 34816
#define A_LO_OFF   34816
#define B_HI_OFF   69632             // 256*SA*2 = 69632
#define B_LO_OFF   139264
#define WCM_OFF    208896            // 8192
#define BR_OFF     217088
#define BZ_OFF     217344
#define BNI_OFF    217600
#define BNH_OFF    217856
#define BP_OFF     218112
#define WO_OFF     218368            // 768
#define PRED_OFF   219136            // 128*3*4 = 1536
#define SMEM_TOTAL 220672

// ---------------- helpers ----------------
__device__ __forceinline__ void red4(float4* addr, float4 v) {
    asm volatile("red.global.add.v4.f32 [%0], {%1,%2,%3,%4};"
                 :: "l"(addr), "f"(v.x), "f"(v.y), "f"(v.z), "f"(v.w) : "memory");
}
__device__ __forceinline__ void red1(float* addr, float v) {
    asm volatile("red.global.add.f32 [%0], %1;" :: "l"(addr), "f"(v) : "memory");
}
__device__ __forceinline__ float sigf(float x) {
    float e = __expf(-x);
    return __fdividef(1.f, 1.f + e);
}
__device__ __forceinline__ float tanhfast(float x) {
    float e = __expf(-2.f * x);
    return __fdividef(1.f - e, 1.f + e);
}
__device__ __forceinline__ uint32_t smem_u32(const void* p) {
    uint32_t a;
    asm("{ .reg .u64 t; cvta.to.shared.u64 t, %1; cvt.u32.u64 %0, t; }" : "=r"(a) : "l"(p));
    return a;
}
__device__ __forceinline__ void ldsm4(uint32_t& r0, uint32_t& r1, uint32_t& r2, uint32_t& r3,
                                      uint32_t addr) {
    asm volatile("ldmatrix.sync.aligned.m8n8.x4.shared.b16 {%0,%1,%2,%3}, [%4];"
                 : "=r"(r0), "=r"(r1), "=r"(r2), "=r"(r3) : "r"(addr));
}
__device__ __forceinline__ void mma16816(float* c, uint32_t a0, uint32_t a1, uint32_t a2,
                                         uint32_t a3, uint32_t b0, uint32_t b1) {
    asm volatile("mma.sync.aligned.m16n8k16.row.col.f32.bf16.bf16.f32 "
                 "{%0,%1,%2,%3}, {%4,%5,%6,%7}, {%8,%9}, {%0,%1,%2,%3};"
                 : "+f"(c[0]), "+f"(c[1]), "+f"(c[2]), "+f"(c[3])
                 : "r"(a0), "r"(a1), "r"(a2), "r"(a3), "r"(b0), "r"(b1));
}
// write bf16 hi/lo pair (cols col,col+1; col even) into A tiles, padded row-major
__device__ __forceinline__ void write_a(char* smem, int row, int col, float v0, float v1) {
    __nv_bfloat16 h0 = __float2bfloat16(v0);
    __nv_bfloat16 h1 = __float2bfloat16(v1);
    __nv_bfloat16 l0 = __float2bfloat16(v0 - __bfloat162float(h0));
    __nv_bfloat16 l1 = __float2bfloat16(v1 - __bfloat162float(h1));
    uint32_t byte = (uint32_t)row * (SA * 2) + (uint32_t)col * 2;
    uint32_t hi = (uint32_t)__bfloat16_as_ushort(h0) | ((uint32_t)__bfloat16_as_ushort(h1) << 16);
    uint32_t lo = (uint32_t)__bfloat16_as_ushort(l0) | ((uint32_t)__bfloat16_as_ushort(l1) << 16);
    *(uint32_t*)(smem + A_HI_OFF + byte) = hi;
    *(uint32_t*)(smem + A_LO_OFF + byte) = lo;
}

// ---------------- kernel 1: zero scratch + precompute all weights ----------------
__global__ void k_pre(const float* __restrict__ Wc, const float* __restrict__ bc,
                      const float* __restrict__ Wm, const float* __restrict__ bm,
                      const float* __restrict__ Wih, const float* __restrict__ Whh,
                      const float* __restrict__ bih, const float* __restrict__ bhh) {
    int i = blockIdx.x * 256 + threadIdx.x;
    float4 z = make_float4(0.f, 0.f, 0.f, 0.f);
    if (i < 1600000) { g_she[i] = z; return; }
    int j = i - 1600000;
    if (j < 800000) { g_agg[j] = z; return; }
    int k = i - 2400000;
    if (k >= 0 && k < 100000) { ((float4*)g_bdeg)[k] = z; return; }
    int l = i - 2500000;
    if (l >= 0 && l < 50000) { ((float4*)g_ddeg)[l] = z; return; }
    int m = i - 2550000;
    if (m >= 0 && m < 2112) {
        if (m < 2048) {
            int t = m >> 10, rem = m & 1023, ii = rem >> 6, jj = rem & 63;
            float acc = 0.f;
            for (int kk = 0; kk < 64; kk++)
                acc += Wc[(t * 16 + ii) * 64 + kk] * Wm[(t * 64 + kk) * 64 + jj];
            g_Wcm[m] = acc;
        } else {
            int jj = m - 2048;
            float acc = bm[jj];
            for (int t = 0; t < 2; t++)
                for (int kk = 0; kk < 64; kk++)
                    acc += bc[t * 64 + kk] * Wm[(t * 64 + kk) * 64 + jj];
            g_bprime[jj] = acc;
        }
        return;
    }
    int p = i - 2552112;
    if (p >= 0 && p < 32768) {
        // B[n][k]: n = gate col (0..255), k = input (0..127).
        // n 0-63: r | 64-127: z | 128-191: i_n (H only) | 192-255: h_n (hprev only)
        int n = p >> 7, kk = p & 127;
        float w = 0.f;
        if (kk < 64) {
            if (n < 192) w = Wih[n * 64 + kk];
        } else {
            if (n < 128) w = Whh[n * 64 + (kk - 64)];
            else if (n >= 192) w = Whh[(n - 64) * 64 + (kk - 64)];
        }
        __nv_bfloat16 hi = __float2bfloat16(w);
        __nv_bfloat16 lo = __float2bfloat16(w - __bfloat162float(hi));
        g_Bh[n * SA + kk] = hi;
        g_Bl[n * SA + kk] = lo;
        if (p < 64) {
            g_br[p]  = bih[p] + bhh[p];
            g_bz[p]  = bih[64 + p] + bhh[64 + p];
            g_bni[p] = bih[128 + p];
            g_bnh[p] = bhh[128 + p];
        }
    }
}

// ---------------- kernel 2: scatter x -> hyperedges + degree counts ----------------
__global__ void k_scat1(const int* __restrict__ en, const int* __restrict__ eh,
                        const int* __restrict__ ea, const float4* __restrict__ x4) {
    int gid = blockIdx.x * 256 + threadIdx.x;
    int e = gid >> 2;
    if (e >= NEDGE) return;
    int sub = gid & 3;
    int node = __ldg(en + e), he = __ldg(eh + e), t = __ldg(ea + e);
    float4 v = x4[node * 4 + sub];
    red4(&g_she[(t * MHE + he) * 4 + sub], v);
    if (sub == 0) red1(&g_bdeg[t * MHE + he], 1.f);
    else if (sub == 1) red1(&g_ddeg[t * NNODES + node], 1.f);
}

// ---------------- kernel 3: hyperedges -> nodes ----------------
__global__ void k_scat2(const int* __restrict__ en, const int* __restrict__ eh,
                        const int* __restrict__ ea) {
    int gid = blockIdx.x * 256 + threadIdx.x;
    int e = gid >> 2;
    if (e >= NEDGE) return;
    int sub = gid & 3;
    int node = __ldg(en + e), he = __ldg(eh + e), t = __ldg(ea + e);
    float c = __ldg(&g_bdeg[t * MHE + he]);
    float bi = 1.0f / c;
    float4 v = g_she[(t * MHE + he) * 4 + sub];
    v.x *= bi; v.y *= bi; v.z *= bi; v.w *= bi;
    red4(&g_agg[(t * NNODES + node) * 4 + sub], v);
}

// ---------------- kernel 4: persistent HMMA mix+GRU+pred ----------------
// 148 CTAs x 256 threads (8 warps). Warp tile = 64 rows x 64 gate-cols (interleaved),
// so B fragments are shared across only 2 warps and A across 4 -> half the LDS traffic.
__global__ __launch_bounds__(256, 1) void k_gru(const float* __restrict__ hprev,
                                                const float* __restrict__ Wout,
                                                const float* __restrict__ bout,
                                                float* __restrict__ out, int Nn) {
    extern __shared__ char smem[];
    const uint32_t sbase = smem_u32(smem);
    const int tid = threadIdx.x;
    const int wid = tid >> 5;
    const int lane = tid & 31;

    // ---- stage constants once per CTA ----
    {
        const uint4* bh = reinterpret_cast<const uint4*>(g_Bh);
        const uint4* bl = reinterpret_cast<const uint4*>(g_Bl);
        uint4* sbh = reinterpret_cast<uint4*>(smem + B_HI_OFF);
        uint4* sbl = reinterpret_cast<uint4*>(smem + B_LO_OFF);
        for (int i = tid; i < 4352; i += 256) { sbh[i] = bh[i]; sbl[i] = bl[i]; }
        float4* swc = reinterpret_cast<float4*>(smem + WCM_OFF);
        const float4* gwc = reinterpret_cast<const float4*>(g_Wcm);
        for (int i = tid; i < 512; i += 256) swc[i] = gwc[i];
        if (tid < 64) {
            ((float*)(smem + BR_OFF))[tid]  = g_br[tid];
            ((float*)(smem + BZ_OFF))[tid]  = g_bz[tid];
            ((float*)(smem + BNI_OFF))[tid] = g_bni[tid];
            ((float*)(smem + BNH_OFF))[tid] = g_bnh[tid];
            ((float*)(smem + BP_OFF))[tid]  = g_bprime[tid];
        }
        if (tid < 192) ((float*)(smem + WO_OFF))[tid] = Wout[(tid / 3) * 64 + (tid % 3)];
    }
    __syncthreads();

    const float* f_br  = (const float*)(smem + BR_OFF);
    const float* f_bz  = (const float*)(smem + BZ_OFF);
    const float* f_bni = (const float*)(smem + BNI_OFF);
    const float* f_bnh = (const float*)(smem + BNH_OFF);
    const float* f_bp  = (const float*)(smem + BP_OFF);
    const float* f_wcm = (const float*)(smem + WCM_OFF);
    const float* f_wo  = (const float*)(smem + WO_OFF);
    float* pred_sm     = (float*)(smem + PRED_OFF);
    const float bo0 = __ldg(bout + 0), bo1 = __ldg(bout + 1), bo2 = __ldg(bout + 2);

    // stage-A mapping
    const int row  = tid >> 1;          // 0..127
    const int j0m  = (tid & 1) * 32;

    // GEMM mapping: warp = 64 rows x 64 interleaved gate-cols
    const int rw   = (wid & 1) * 64;    // row stripe base
    const int cblk = wid >> 1;          // 0..3 -> j block 16*cblk
    const int g    = lane >> 2;
    const int tid4 = lane & 3;
    const uint32_t a_row_byte  = (uint32_t)(rw + (lane & 15)) * (SA * 2) + (uint32_t)(lane >> 4) * 16;
    const uint32_t b_pair_byte = (uint32_t)((lane & 7) + ((lane >> 4) << 3)) * (SA * 2)
                               + (uint32_t)((lane >> 3) & 1) * 16;

    const int ntiles = (Nn + 127) >> 7;
    for (int tile = blockIdx.x; tile < ntiles; tile += gridDim.x) {
        const int nbase = tile << 7;

        // ============ stage A: build X_cat [128][128] bf16 hi/lo + zero pred_sm ============
        {
            for (int i = tid; i < 384; i += 256) pred_sm[i] = 0.f;
            const int gn = nbase + row;
            const bool valid = gn < Nn;
            float a[32];
            if (valid) {
                float c0 = __ldg(&g_ddeg[gn]), c1 = __ldg(&g_ddeg[NNODES + gn]);
                float d0 = (c0 > 0.f) ? 1.f / c0 : 0.f;
                float d1 = (c1 > 0.f) ? 1.f / c1 : 0.f;
#pragma unroll
                for (int q = 0; q < 4; q++) {
                    float4 v = g_agg[(size_t)gn * 4 + q];
                    a[q * 4 + 0] = v.x * d0; a[q * 4 + 1] = v.y * d0;
                    a[q * 4 + 2] = v.z * d0; a[q * 4 + 3] = v.w * d0;
                    float4 w = g_agg[(size_t)(NNODES + gn) * 4 + q];
                    a[16 + q * 4 + 0] = w.x * d1; a[16 + q * 4 + 1] = w.y * d1;
                    a[16 + q * 4 + 2] = w.z * d1; a[16 + q * 4 + 3] = w.w * d1;
                }
            } else {
#pragma unroll
                for (int q = 0; q < 32; q++) a[q] = 0.f;
            }
            float acc[32];
#pragma unroll
            for (int s = 0; s < 32; s++) acc[s] = f_bp[j0m + s];
#pragma unroll
            for (int i2 = 0; i2 < 32; i2++) {
                float av = a[i2];
                const float* w = f_wcm + i2 * 64 + j0m;
#pragma unroll
                for (int s = 0; s < 32; s++) acc[s] += av * w[s];
            }
#pragma unroll
            for (int jp = 0; jp < 32; jp += 2)
                write_a(smem, row, j0m + jp, fmaxf(acc[jp], 0.f), fmaxf(acc[jp + 1], 0.f));
            const float4* hq = (const float4*)(hprev + (size_t)gn * 64 + j0m);
#pragma unroll
            for (int q = 0; q < 8; q++) {
                float4 v = valid ? __ldg(hq + q) : make_float4(0.f, 0.f, 0.f, 0.f);
                write_a(smem, row, 64 + j0m + q * 4,     v.x, v.y);
                write_a(smem, row, 64 + j0m + q * 4 + 2, v.z, v.w);
            }
        }
        __syncthreads();

        // ============ GEMM: warp computes rows rw..rw+63 x interleaved 64 gate-cols ============
        float acc[128];
#pragma unroll
        for (int s = 0; s < 128; s++) acc[s] = 0.f;

#pragma unroll
        for (int ks = 0; ks < 8; ks++) {
            uint32_t bh[16], bl[16];
#pragma unroll
            for (int p = 0; p < 4; p++) {
                uint32_t baddr = sbase + b_pair_byte
                               + (uint32_t)(p * 64 + 16 * cblk) * (SA * 2) + (uint32_t)ks * 32;
                ldsm4(bh[p * 4], bh[p * 4 + 1], bh[p * 4 + 2], bh[p * 4 + 3], baddr + B_HI_OFF);
                ldsm4(bl[p * 4], bl[p * 4 + 1], bl[p * 4 + 2], bl[p * 4 + 3], baddr + B_LO_OFF);
            }
#pragma unroll
            for (int mt = 0; mt < 4; mt++) {
                uint32_t aaddr = sbase + a_row_byte + (uint32_t)(mt * 16) * (SA * 2)
                               + (uint32_t)ks * 32;
                uint32_t ah0, ah1, ah2, ah3, al0, al1, al2, al3;
                ldsm4(ah0, ah1, ah2, ah3, aaddr + A_HI_OFF);
                ldsm4(al0, al1, al2, al3, aaddr + A_LO_OFF);
#pragma unroll
                for (int ntl = 0; ntl < 8; ntl++) {
                    const int bi = (ntl >> 1) * 4 + (ntl & 1) * 2;
                    float* cc = acc + (mt * 8 + ntl) * 4;
                    mma16816(cc, ah0, ah1, ah2, ah3, bh[bi], bh[bi + 1]);
                    mma16816(cc, ah0, ah1, ah2, ah3, bl[bi], bl[bi + 1]);
                    mma16816(cc, al0, al1, al2, al3, bh[bi], bh[bi + 1]);
                }
            }
        }

        // ============ epilogue: GRU combine + store + pred (smem atomics) ============
#pragma unroll
        for (int mt = 0; mt < 4; mt++) {
#pragma unroll
            for (int rsel = 0; rsel < 2; rsel++) {
                const int lrow = rw + mt * 16 + g + rsel * 8;
                const int gn = nbase + lrow;
                const bool ev = gn < Nn;
                const int ci = rsel * 2;
                const int j1 = 16 * cblk + tid4 * 2;
                float2 hp1 = ev ? __ldg((const float2*)(hprev + (size_t)gn * 64 + j1))
                                : make_float2(0.f, 0.f);
                float2 hp2 = ev ? __ldg((const float2*)(hprev + (size_t)gn * 64 + j1 + 8))
                                : make_float2(0.f, 0.f);
                float res[4];
                float p0 = 0.f, p1 = 0.f, p2 = 0.f;
#pragma unroll
                for (int p = 0; p < 2; p++) {
#pragma unroll
                    for (int s = 0; s < 2; s++) {
                        const int jc = 16 * cblk + 8 * p + tid4 * 2 + s;
                        float rv = acc[(mt * 8 + 0 + p) * 4 + ci + s] + f_br[jc];
                        float zv = acc[(mt * 8 + 2 + p) * 4 + ci + s] + f_bz[jc];
                        float iv = acc[(mt * 8 + 4 + p) * 4 + ci + s] + f_bni[jc];
                        float hv = acc[(mt * 8 + 6 + p) * 4 + ci + s] + f_bnh[jc];
                        float r = sigf(rv);
                        float z = sigf(zv);
                        float nn = tanhfast(iv + r * hv);
                        float hpv = p ? (s ? hp2.y : hp2.x) : (s ? hp1.y : hp1.x);
                        float rr = (1.f - z) * nn + z * hpv;
                        res[p * 2 + s] = rr;
                        p0 += rr * f_wo[jc * 3 + 0];
                        p1 += rr * f_wo[jc * 3 + 1];
                        p2 += rr * f_wo[jc * 3 + 2];
                    }
                }
                if (ev) {
                    *(float2*)(out + (size_t)gn * 64 + j1)     = make_float2(res[0], res[1]);
                    *(float2*)(out + (size_t)gn * 64 + j1 + 8) = make_float2(res[2], res[3]);
                }
#pragma unroll
                for (int m2 = 1; m2 < 4; m2 <<= 1) {
                    p0 += __shfl_xor_sync(0xffffffffu, p0, m2);
                    p1 += __shfl_xor_sync(0xffffffffu, p1, m2);
                    p2 += __shfl_xor_sync(0xffffffffu, p2, m2);
                }
                if (tid4 == 0) {
                    atomicAdd(&pred_sm[lrow * 3 + 0], p0);
                    atomicAdd(&pred_sm[lrow * 3 + 1], p1);
                    atomicAdd(&pred_sm[lrow * 3 + 2], p2);
                }
            }
        }
        __syncthreads();
        if (tid < 128) {
            const int gn = nbase + tid;
            if (gn < Nn) {
                float* pp = out + (size_t)Nn * 64 + (size_t)gn * 3;
                pp[0] = pred_sm[tid * 3 + 0] + bo0;
                pp[1] = pred_sm[tid * 3 + 1] + bo1;
                pp[2] = pred_sm[tid * 3 + 2] + bo2;
            }
        }
        __syncthreads();   // A smem + pred_sm reuse next tile
    }
}

// ---------------- launch ----------------
extern "C" void kernel_launch(void* const* d_in, const int* in_sizes, int n_in,
                              void* d_out, int out_size) {
    const float* x     = (const float*)d_in[0];
    const float* hprev = (const float*)d_in[1];
    const int*   en    = (const int*)d_in[2];
    const int*   eh    = (const int*)d_in[3];
    const int*   ea    = (const int*)d_in[4];
    const float* Wconv = (const float*)d_in[5];
    const float* bconv = (const float*)d_in[6];
    const float* Wmix  = (const float*)d_in[7];
    const float* bmix  = (const float*)d_in[8];
    const float* Wih   = (const float*)d_in[9];
    const float* Whh   = (const float*)d_in[10];
    const float* bih   = (const float*)d_in[11];
    const float* bhh   = (const float*)d_in[12];
    const float* Wout  = (const float*)d_in[13];
    const float* bout  = (const float*)d_in[14];
    float* out = (float*)d_out;

    (void)in_sizes; (void)n_in; (void)out_size;

    k_pre<<<10098, 256>>>(Wconv, bconv, Wmix, bmix, Wih, Whh, bih, bhh);
    k_scat1<<<31250, 256>>>(en, eh, ea, (const float4*)x);
    k_scat2<<<31250, 256>>>(en, eh, ea);

    cudaFuncSetAttribute(k_gru, cudaFuncAttributeMaxDynamicSharedMemorySize, SMEM_TOTAL);
    k_gru<<<148, 256, SMEM_TOTAL>>>(hprev, Wout, bout, out, NNODES);
}